// round 1
// baseline (speedup 1.0000x reference)
#include <cuda_runtime.h>
#include <stdint.h>

// Problem constants
#define B     1024
#define S     2048
#define R1    20000
#define R2    40000

#define MAIN_THREADS 512
#define SPECIES_PER_THREAD (S / MAIN_THREADS)   // 4

// ---------------- static device scratch (no runtime allocation) ----------------
__device__ int       g_counts1[S];
__device__ int       g_counts2[S];
__device__ int       g_offs1[S + 1];
__device__ int       g_offs2[S + 1];
__device__ int       g_cur1[S];
__device__ int       g_cur2[S];
__device__ uint32_t  g_csr1[R1];        // ra | (rid << 11)
__device__ uint16_t  g_csr2_rid[R2];    // rid (< 40000, fits u16)
__device__ uint32_t  g_csr2_ab[R2];     // ra | (rb << 16)

// ---------------- prep kernels ----------------

__global__ void init_counts_kernel() {
    int i = blockIdx.x * blockDim.x + threadIdx.x;
    if (i < S) { g_counts1[i] = 0; g_counts2[i] = 0; }
}

__global__ void hist_kernel(const int* __restrict__ inds_1p,
                            const int* __restrict__ inds_2p) {
    int i = blockIdx.x * blockDim.x + threadIdx.x;
    if (i < R1) {
        atomicAdd(&g_counts1[inds_1p[i]], 1);
    } else if (i < R1 + R2) {
        atomicAdd(&g_counts2[inds_2p[i - R1]], 1);
    }
}

// Single-CTA inclusive scan (Hillis-Steele, double buffered) over 2048 bins,
// done twice (counts1 -> offs1/cur1, counts2 -> offs2/cur2).
__global__ void scan_kernel() {
    __shared__ int buf[2][S];
    const int tid = threadIdx.x;   // 1024 threads, 2 elems each

    for (int pass = 0; pass < 2; ++pass) {
        const int* cnt = pass == 0 ? g_counts1 : g_counts2;
        int*       offs = pass == 0 ? g_offs1 : g_offs2;
        int*       cur  = pass == 0 ? g_cur1  : g_cur2;

        buf[0][tid]        = cnt[tid];
        buf[0][tid + 1024] = cnt[tid + 1024];
        __syncthreads();

        int src = 0;
        for (int off = 1; off < S; off <<= 1) {
            int i0 = tid, i1 = tid + 1024;
            int v0 = buf[src][i0] + (i0 >= off ? buf[src][i0 - off] : 0);
            int v1 = buf[src][i1] + (i1 >= off ? buf[src][i1 - off] : 0);
            __syncthreads();
            buf[1 - src][i0] = v0;
            buf[1 - src][i1] = v1;
            __syncthreads();
            src ^= 1;
        }
        // exclusive offsets: offs[i] = incl[i-1], offs[0] = 0
        if (tid == 0) offs[0] = 0;
        offs[tid + 1]        = buf[src][tid];
        offs[tid + 1 + 1024] = buf[src][tid + 1024];
        cur[tid]        = (tid == 0)        ? 0 : buf[src][tid - 1];
        cur[tid + 1024] = buf[src][tid + 1023];
        __syncthreads();
    }
}

__global__ void scatter_kernel(const int* __restrict__ inds_1r,
                               const int* __restrict__ inds_1p,
                               const int* __restrict__ inds_2r,
                               const int* __restrict__ inds_2p) {
    int i = blockIdx.x * blockDim.x + threadIdx.x;
    if (i < R1) {
        int p = inds_1p[i];
        int pos = atomicAdd(&g_cur1[p], 1);
        g_csr1[pos] = (uint32_t)inds_1r[i] | ((uint32_t)i << 11);
    } else if (i < R1 + R2) {
        int j = i - R1;
        int p = inds_2p[j];
        int pos = atomicAdd(&g_cur2[p], 1);
        g_csr2_rid[pos] = (uint16_t)j;
        g_csr2_ab[pos]  = (uint32_t)inds_2r[2 * j] | ((uint32_t)inds_2r[2 * j + 1] << 16);
    }
}

// ---------------- main kernel ----------------
// One CTA per batch row. SMEM: y row (2048 f32) + rate buffer (40000 f32).
// Phase A: stage rates_1st row, consume CSR1 (register accumulation).
// Phase B: stage rates_2nd row into the same buffer, consume CSR2.
// Zero atomics; each thread owns 4 output species.

#define SMEM_FLOATS (S + R2)          // 42048 floats = 168192 bytes

__global__ __launch_bounds__(MAIN_THREADS, 1)
void reaction_main_kernel(const float* __restrict__ y_in,
                          const float* __restrict__ rates_1st,
                          const float* __restrict__ rates_2nd,
                          float* __restrict__ y_out) {
    extern __shared__ float sm[];
    float* y_s  = sm;        // [S]
    float* rbuf = sm + S;    // [R2] (phase A uses first R1 floats)

    const int b   = blockIdx.x;
    const int tid = threadIdx.x;

    // Load y row (2048 floats -> exactly one float4 per thread)
    {
        const float4* src = (const float4*)(y_in + (size_t)b * S);
        ((float4*)y_s)[tid] = src[tid];
    }

    // ---- Phase A: first-order reactions ----
    {
        const float4* src = (const float4*)(rates_1st + (size_t)b * R1);
        #pragma unroll
        for (int i = tid; i < R1 / 4; i += MAIN_THREADS)
            ((float4*)rbuf)[i] = src[i];
    }
    __syncthreads();

    float acc[SPECIES_PER_THREAD];
    #pragma unroll
    for (int k = 0; k < SPECIES_PER_THREAD; ++k) {
        const int s  = tid + k * MAIN_THREADS;
        const int e0 = g_offs1[s];
        const int e1 = g_offs1[s + 1];
        float a = 0.0f;
        for (int e = e0; e < e1; ++e) {
            uint32_t v = g_csr1[e];
            a += y_s[v & 2047u] * rbuf[v >> 11];
        }
        acc[k] = a;
    }
    __syncthreads();   // all phase-A rbuf reads done before overwrite

    // ---- Phase B: second-order reactions ----
    {
        const float4* src = (const float4*)(rates_2nd + (size_t)b * R2);
        #pragma unroll
        for (int i = tid; i < R2 / 4; i += MAIN_THREADS)
            ((float4*)rbuf)[i] = src[i];
    }
    __syncthreads();

    #pragma unroll
    for (int k = 0; k < SPECIES_PER_THREAD; ++k) {
        const int s  = tid + k * MAIN_THREADS;
        const int e0 = g_offs2[s];
        const int e1 = g_offs2[s + 1];
        float a = acc[k];
        for (int e = e0; e < e1; ++e) {
            int      rid = g_csr2_rid[e];
            uint32_t ab  = g_csr2_ab[e];
            a += y_s[ab & 2047u] * y_s[ab >> 16] * rbuf[rid];
        }
        acc[k] = a;
    }

    // ---- write out ----
    #pragma unroll
    for (int k = 0; k < SPECIES_PER_THREAD; ++k)
        y_out[(size_t)b * S + tid + k * MAIN_THREADS] = acc[k];
}

// ---------------- launch ----------------

extern "C" void kernel_launch(void* const* d_in, const int* in_sizes, int n_in,
                              void* d_out, int out_size) {
    const float* y_in      = (const float*)d_in[0];
    const float* rates_1st = (const float*)d_in[1];
    const float* rates_2nd = (const float*)d_in[2];
    const int*   inds_1r   = (const int*)d_in[3];
    const int*   inds_1p   = (const int*)d_in[4];
    const int*   inds_2r   = (const int*)d_in[5];
    const int*   inds_2p   = (const int*)d_in[6];
    float*       y_out     = (float*)d_out;

    static_assert(SMEM_FLOATS * sizeof(float) == 168192, "smem size");
    cudaFuncSetAttribute(reaction_main_kernel,
                         cudaFuncAttributeMaxDynamicSharedMemorySize,
                         SMEM_FLOATS * (int)sizeof(float));

    // CSR build (runs every launch; deterministic work, rebuilds from inputs)
    init_counts_kernel<<<(S + 255) / 256, 256>>>();
    hist_kernel<<<(R1 + R2 + 255) / 256, 256>>>(inds_1p, inds_2p);
    scan_kernel<<<1, 1024>>>();
    scatter_kernel<<<(R1 + R2 + 255) / 256, 256>>>(inds_1r, inds_1p, inds_2r, inds_2p);

    // Main pass: one CTA per batch row, atomic-free register accumulation
    reaction_main_kernel<<<B, MAIN_THREADS, SMEM_FLOATS * sizeof(float)>>>(
        y_in, rates_1st, rates_2nd, y_out);
}